// round 12
// baseline (speedup 1.0000x reference)
#include <cuda_runtime.h>
#include <cstdint>

#define N_NODES 50000
#define N_EDGES 800000
#define F_X 128
#define F_E 128
#define HIDDEN 512
#define F_OUT 128

// ---------------- scratch (static device globals; no runtime alloc) --------
__device__ float    g_agg[(size_t)N_NODES * F_E];              // 25.6 MB fp32
__device__ uint32_t g_A[(size_t)N_NODES * (F_E + F_X)];        // 51.2 MB tf32 [50000][256]
__device__ uint32_t g_h[(size_t)N_NODES * HIDDEN];             // 102.4 MB tf32 bits
__device__ uint32_t g_W1t[(size_t)HIDDEN * (F_E + F_X)];       // W1^T tf32 [512][256]
__device__ uint32_t g_W2t[(size_t)F_OUT * HIDDEN];             // W2^T tf32 [128][512]

__device__ __forceinline__ uint32_t f2tf32(float f) {
    uint32_t r; asm("cvt.rna.tf32.f32 %0, %1;" : "=r"(r) : "f"(f)); return r;
}
__device__ __forceinline__ uint32_t smem_u32(const void* p) {
    uint32_t a;
    asm("{ .reg .u64 t; cvta.to.shared.u64 t, %1; cvt.u32.u64 %0, t; }"
        : "=r"(a) : "l"(p));
    return a;
}

// ---------------------------------------------------------------------------
// scatter-add, one warp per edge, red.global.add.v4.f32
// ---------------------------------------------------------------------------
__global__ void __launch_bounds__(256) scatter_edges_kernel(
    const float4* __restrict__ edge_attr, const int* __restrict__ receivers)
{
    int gt = blockIdx.x * blockDim.x + threadIdx.x;
    int edge = gt >> 5;
    int lane = gt & 31;
    if (edge >= N_EDGES) return;

    int r = __ldg(receivers + edge);
    float4 v = edge_attr[(size_t)edge * 32 + lane];
    float* dst = g_agg + (size_t)r * F_E + lane * 4;
    asm volatile("red.global.add.v4.f32 [%0], {%1,%2,%3,%4};"
                 :: "l"(dst), "f"(v.x), "f"(v.y), "f"(v.z), "f"(v.w)
                 : "memory");
}

// ---------------------------------------------------------------------------
// fused prep — concat(g_agg|nodes)->g_A tf32, W1->W1t, W2->W2t
// ---------------------------------------------------------------------------
#define PREP_NC  (N_NODES * 64)                  // 3,200,000 float4 items
#define PREP_NW1 (HIDDEN * (F_E + F_X))          // 131,072
#define PREP_NW2 (F_OUT * HIDDEN)                // 65,536
#define PREP_TOTAL (PREP_NC + PREP_NW1 + PREP_NW2)

__global__ void __launch_bounds__(256) prep_kernel(
    const float4* __restrict__ nodes,
    const float* __restrict__ W1, const float* __restrict__ W2)
{
    int i = blockIdx.x * blockDim.x + threadIdx.x;
    if (i < PREP_NC) {
        int row = i >> 6, c4 = i & 63;
        float4 v = (c4 < 32)
            ? reinterpret_cast<const float4*>(g_agg)[(size_t)row * 32 + c4]
            : nodes[(size_t)row * 32 + (c4 - 32)];
        uint4 t;
        t.x = f2tf32(v.x); t.y = f2tf32(v.y);
        t.z = f2tf32(v.z); t.w = f2tf32(v.w);
        reinterpret_cast<uint4*>(g_A)[i] = t;
    } else if (i < PREP_NC + PREP_NW1) {
        int idx = i - PREP_NC;
        int n = idx >> 8, k = idx & 255;                 // K=256
        g_W1t[idx] = f2tf32(W1[(size_t)k * HIDDEN + n]);
    } else if (i < PREP_TOTAL) {
        int idx = i - PREP_NC - PREP_NW1;
        int n = idx >> 9, k = idx & 511;                 // K=512
        g_W2t[idx] = f2tf32(W2[(size_t)k * F_OUT + n]);
    }
}

// ---------------------------------------------------------------------------
// cp.async 3-stage tf32 mma GEMM, BK=32, XOR-swizzled smem (no padding),
// single barrier per tile, 3 CTAs/SM (launch_bounds(256,3), 73.7KB smem).
// L1=true : BM= 64, BN=128; 8 warps 2m x 4n, warp 32x32. A=g_A K=256.
//           out = g_h (tf32 bits) with bias+ReLU.
// L1=false: BM=128, BN= 64; 8 warps 4m x 2n, warp 32x32. A=g_h K=512.
//           out = Cout fp32 with bias.
// Swizzle: 16B chunk c of row r stored at chunk (c ^ (r&7)).
//   frag bank = ((kc^g)&7)*4 + t4 -> 32 distinct banks. Conflict-free.
// ---------------------------------------------------------------------------
template <bool L1>
__global__ void __launch_bounds__(256, 3)
gemm_pipe_kernel(const uint32_t* __restrict__ Aglob,
                 const uint32_t* __restrict__ Wt,
                 const float* __restrict__ bias,
                 float* __restrict__ Cout)
{
    constexpr int K  = L1 ? (F_E + F_X) : HIDDEN;
    constexpr int N  = L1 ? HIDDEN : F_OUT;
    constexpr int BM = L1 ? 64 : 128;
    constexpr int BN = L1 ? 128 : 64;
    constexpr int M  = N_NODES;
    constexpr int NTILES = K / 32;
    constexpr int STW = (BM + BN) * 32;      // stage words (6144)
    constexpr int ACH = BM / 32;             // A 16B-chunks per thread
    constexpr int BCH = BN / 32;             // B 16B-chunks per thread

    extern __shared__ uint32_t smem[];
    const uint32_t sbase = smem_u32(smem);

    const int tid  = threadIdx.x;
    const int lane = tid & 31;
    const int warp = tid >> 5;
    const int m0 = blockIdx.y * BM;
    const int n0 = blockIdx.x * BN;
    const int warp_m = L1 ? ((warp >> 2) * 32) : ((warp >> 1) * 32);
    const int warp_n = L1 ? ((warp & 3) * 32) : ((warp & 1) * 32);
    const int g  = lane >> 2;
    const int t4 = lane & 3;

    float acc[2][4][4];
    #pragma unroll
    for (int mt = 0; mt < 2; ++mt)
        #pragma unroll
        for (int nt = 0; nt < 4; ++nt)
            #pragma unroll
            for (int i = 0; i < 4; ++i) acc[mt][nt][i] = 0.f;

    auto issue = [&](int tile, int slot) {
        const int k0 = tile * 32;
        uint32_t ab = sbase + (slot * STW) * 4;
        uint32_t bb = ab + (BM * 32) * 4;
        #pragma unroll
        for (int i = 0; i < ACH; ++i) {
            int e = tid + i * 256;
            int r = e >> 3, c = e & 7;
            int ok = (m0 + r) < M ? 16 : 0;
            asm volatile("cp.async.cg.shared.global [%0], [%1], 16, %2;"
                :: "r"(ab + (r * 32 + ((c ^ (r & 7)) << 2)) * 4),
                   "l"(Aglob + (size_t)(m0 + r) * K + k0 + c * 4),
                   "r"(ok) : "memory");
        }
        #pragma unroll
        for (int i = 0; i < BCH; ++i) {
            int e = tid + i * 256;
            int r = e >> 3, c = e & 7;
            asm volatile("cp.async.cg.shared.global [%0], [%1], 16;"
                :: "r"(bb + (r * 32 + ((c ^ (r & 7)) << 2)) * 4),
                   "l"(Wt + (size_t)(n0 + r) * K + k0 + c * 4)
                : "memory");
        }
    };

    issue(0, 0); asm volatile("cp.async.commit_group;" ::: "memory");
    issue(1, 1); asm volatile("cp.async.commit_group;" ::: "memory");

    for (int it = 0; it < NTILES; ++it) {
        asm volatile("cp.async.wait_group 1;" ::: "memory");
        __syncthreads();
        // single barrier: all warps finished compute(it-1), so slot
        // (it+2)%3 == (it-1)%3 is safe to overwrite.
        if (it + 2 < NTILES) issue(it + 2, (it + 2) % 3);
        asm volatile("cp.async.commit_group;" ::: "memory");

        const uint32_t* As = smem + (it % 3) * STW;
        const uint32_t* Bs = As + BM * 32;

        #pragma unroll
        for (int ks = 0; ks < 4; ++ks) {
            const int kc = ks * 2;           // 16B-chunk index of kb
            uint32_t a[2][4], b[4][2];
            #pragma unroll
            for (int mt = 0; mt < 2; ++mt) {
                int mb = warp_m + mt * 16;
                a[mt][0] = As[(mb + g)     * 32 + (((kc    ) ^ g) & 7) * 4 + t4];
                a[mt][1] = As[(mb + g + 8) * 32 + (((kc    ) ^ g) & 7) * 4 + t4];
                a[mt][2] = As[(mb + g)     * 32 + (((kc + 1) ^ g) & 7) * 4 + t4];
                a[mt][3] = As[(mb + g + 8) * 32 + (((kc + 1) ^ g) & 7) * 4 + t4];
            }
            #pragma unroll
            for (int nt = 0; nt < 4; ++nt) {
                int nb = warp_n + nt * 8;
                b[nt][0] = Bs[(nb + g) * 32 + (((kc    ) ^ g) & 7) * 4 + t4];
                b[nt][1] = Bs[(nb + g) * 32 + (((kc + 1) ^ g) & 7) * 4 + t4];
            }
            #pragma unroll
            for (int mt = 0; mt < 2; ++mt)
                #pragma unroll
                for (int nt = 0; nt < 4; ++nt)
                    asm volatile(
                        "mma.sync.aligned.m16n8k8.row.col.f32.tf32.tf32.f32 "
                        "{%0,%1,%2,%3}, {%4,%5,%6,%7}, {%8,%9}, {%0,%1,%2,%3};"
                        : "+f"(acc[mt][nt][0]), "+f"(acc[mt][nt][1]),
                          "+f"(acc[mt][nt][2]), "+f"(acc[mt][nt][3])
                        : "r"(a[mt][0]), "r"(a[mt][1]),
                          "r"(a[mt][2]), "r"(a[mt][3]),
                          "r"(b[nt][0]), "r"(b[nt][1]));
        }
    }

    // ---- epilogue ----
    #pragma unroll
    for (int mt = 0; mt < 2; ++mt) {
        #pragma unroll
        for (int nt = 0; nt < 4; ++nt) {
            int gc = n0 + warp_n + nt * 8 + t4 * 2;
            float2 bv = *reinterpret_cast<const float2*>(bias + gc);
            #pragma unroll
            for (int hh = 0; hh < 2; ++hh) {
                int gr = m0 + warp_m + mt * 16 + g + hh * 8;
                if (gr >= M) continue;
                float ox = acc[mt][nt][hh * 2 + 0] + bv.x;
                float oy = acc[mt][nt][hh * 2 + 1] + bv.y;
                if (L1) {
                    uint2 t;
                    t.x = f2tf32(fmaxf(ox, 0.f));
                    t.y = f2tf32(fmaxf(oy, 0.f));
                    *reinterpret_cast<uint2*>(g_h + (size_t)gr * N + gc) = t;
                } else {
                    float2 o = make_float2(ox, oy);
                    *reinterpret_cast<float2*>(Cout + (size_t)gr * N + gc) = o;
                }
            }
        }
    }
}

// ---------------------------------------------------------------------------
// order: memset(agg) -> scatter -> prep -> gemm1 -> gemm2
// Inputs: nodes, edge_attr, senders, receivers, W1, b1, W2, b2
// ---------------------------------------------------------------------------
extern "C" void kernel_launch(void* const* d_in, const int* in_sizes, int n_in,
                              void* d_out, int out_size)
{
    const float*  nodes     = (const float*)d_in[0];
    const float4* edge_attr = (const float4*)d_in[1];
    const int*    receivers = (const int*)d_in[3];
    const float*  W1        = (const float*)d_in[4];
    const float*  b1        = (const float*)d_in[5];
    const float*  W2        = (const float*)d_in[6];
    const float*  b2        = (const float*)d_in[7];
    float* out = (float*)d_out;

    uint32_t *w1t = nullptr, *w2t = nullptr, *gA = nullptr, *gh = nullptr;
    float* gagg = nullptr;
    cudaGetSymbolAddress((void**)&w1t,  g_W1t);
    cudaGetSymbolAddress((void**)&w2t,  g_W2t);
    cudaGetSymbolAddress((void**)&gA,   g_A);
    cudaGetSymbolAddress((void**)&gh,   g_h);
    cudaGetSymbolAddress((void**)&gagg, g_agg);

    constexpr int SMEM = 3 * 6144 * 4;    // 73,728 B (both configs)

    static bool attr_set = false;
    if (!attr_set) {
        cudaFuncSetAttribute(gemm_pipe_kernel<true>,
                             cudaFuncAttributeMaxDynamicSharedMemorySize, SMEM);
        cudaFuncSetAttribute(gemm_pipe_kernel<false>,
                             cudaFuncAttributeMaxDynamicSharedMemorySize, SMEM);
        attr_set = true;
    }

    // 1) zero agg via memset node
    cudaMemsetAsync(gagg, 0, (size_t)N_NODES * F_E * sizeof(float));

    // 2) scatter
    {
        long long total = (long long)N_EDGES * 32;
        int blocks = (int)((total + 255) / 256);
        scatter_edges_kernel<<<blocks, 256>>>(edge_attr, receivers);
    }
    // 3) prep
    prep_kernel<<<(PREP_TOTAL + 255) / 256, 256>>>(
        (const float4*)nodes, W1, W2);
    // 4) gemm1: BM=64 -> grid (4, 782)
    {
        dim3 grid(HIDDEN / 128, (N_NODES + 63) / 64);
        gemm_pipe_kernel<true><<<grid, 256, SMEM>>>(gA, w1t, b1, nullptr);
    }
    // 5) gemm2: BM=128, BN=64 -> grid (2, 391)
    {
        dim3 grid(F_OUT / 64, (N_NODES + 127) / 128);
        gemm_pipe_kernel<false><<<grid, 256, SMEM>>>(gh, w2t, b2, out);
    }
}

// round 13
// speedup vs baseline: 1.4833x; 1.4833x over previous
#include <cuda_runtime.h>
#include <cstdint>

#define N_NODES 50000
#define N_EDGES 800000
#define F_X 128
#define F_E 128
#define HIDDEN 512
#define F_OUT 128
#define M_BLKS 3128                    // ceil(50000/16) padded to 128-row CTAs

// ---------------- scratch (static device globals; no runtime alloc) --------
// FRAG-A layout: word(r,c) = ((r>>4)*(K/8) + (c>>3))*128
//                            + (4*(r&7)+(c&3))*4 + ((c>>2)&1)*2 + ((r>>3)&1)
// FRAG-B layout: word(n,k) = ((n>>3)*(K/16) + (k>>4))*128
//                            + (4*(n&7)+(k&3))*4 + ((k>>3)&1)*2 + ((k>>2)&1)
__device__ float    g_agg[(size_t)N_NODES * F_E];                 // 25.6 MB
__device__ uint32_t g_A[(size_t)M_BLKS * 32 * 128];               // 51.3 MB, K=256
__device__ uint32_t g_h[(size_t)M_BLKS * 64 * 128];               // 102.5 MB, K=512
__device__ uint32_t g_W1t[(size_t)HIDDEN * (F_E + F_X)];          // FRAG-B K=256
__device__ uint32_t g_W2t[(size_t)F_OUT * HIDDEN];                // FRAG-B K=512

__device__ __forceinline__ uint32_t f2tf32(float f) {
    uint32_t r; asm("cvt.rna.tf32.f32 %0, %1;" : "=r"(r) : "f"(f)); return r;
}
__device__ __forceinline__ uint32_t smem_u32(const void* p) {
    uint32_t a;
    asm("{ .reg .u64 t; cvta.to.shared.u64 t, %1; cvt.u32.u64 %0, t; }"
        : "=r"(a) : "l"(p));
    return a;
}

// ---------------------------------------------------------------------------
// scatter-add, one warp per edge, red.global.add.v4.f32
// ---------------------------------------------------------------------------
__global__ void __launch_bounds__(256) scatter_edges_kernel(
    const float4* __restrict__ edge_attr, const int* __restrict__ receivers)
{
    int gt = blockIdx.x * blockDim.x + threadIdx.x;
    int edge = gt >> 5;
    int lane = gt & 31;
    if (edge >= N_EDGES) return;

    int r = __ldg(receivers + edge);
    float4 v = edge_attr[(size_t)edge * 32 + lane];
    float* dst = g_agg + (size_t)r * F_E + lane * 4;
    asm volatile("red.global.add.v4.f32 [%0], {%1,%2,%3,%4};"
                 :: "l"(dst), "f"(v.x), "f"(v.y), "f"(v.z), "f"(v.w)
                 : "memory");
}

// ---------------------------------------------------------------------------
// prep: build FRAG-A g_A from [agg|nodes], FRAG-B g_W1t / g_W2t.
// item = one 16B chunk (= one lane's 4 fragment words).
// ---------------------------------------------------------------------------
#define PREP_NC   (3125 * 32 * 32)               // 3,200,000 A chunks
#define PREP_NW1  ((HIDDEN / 8) * (256 / 16) * 32)   // 32768
#define PREP_NW2  ((F_OUT / 8) * (512 / 16) * 32)    // 16384
#define PREP_TOTAL (PREP_NC + PREP_NW1 + PREP_NW2)

__global__ void __launch_bounds__(256) prep_kernel(
    const float* __restrict__ nodes,
    const float* __restrict__ W1, const float* __restrict__ W2)
{
    int j = blockIdx.x * blockDim.x + threadIdx.x;
    if (j < PREP_NC) {
        // A chunk: a = mtile, b = k8-block, l = lane
        int a = j >> 10, b = (j >> 5) & 31, l = j & 31;
        int gg = l >> 2, t4 = l & 3;
        int r = a * 16 + gg;
        int c = b * 8 + t4;
        const float* s0 = (c < F_E) ? (g_agg + c) : (nodes + c - F_E);
        const float* s1 = (c + 4 < F_E) ? (g_agg + c + 4) : (nodes + c + 4 - F_E);
        uint4 t;
        t.x = f2tf32(s0[(size_t)r * 128]);           // (r,   c)
        t.y = f2tf32(s0[(size_t)(r + 8) * 128]);     // (r+8, c)
        t.z = f2tf32(s1[(size_t)r * 128]);           // (r,   c+4)
        t.w = f2tf32(s1[(size_t)(r + 8) * 128]);     // (r+8, c+4)
        reinterpret_cast<uint4*>(g_A)[j] = t;
    } else if (j < PREP_NC + PREP_NW1) {
        int idx = j - PREP_NC;
        int blk = idx >> 5, l = idx & 31;
        int n8 = blk >> 4, kb = blk & 15;            // K/16 = 16
        int n = n8 * 8 + (l >> 2), t4 = l & 3;
        int k0 = kb * 16 + t4;
        uint4 t;
        t.x = f2tf32(W1[(size_t)(k0     ) * HIDDEN + n]);
        t.y = f2tf32(W1[(size_t)(k0 +  4) * HIDDEN + n]);
        t.z = f2tf32(W1[(size_t)(k0 +  8) * HIDDEN + n]);
        t.w = f2tf32(W1[(size_t)(k0 + 12) * HIDDEN + n]);
        reinterpret_cast<uint4*>(g_W1t)[idx] = t;
    } else if (j < PREP_TOTAL) {
        int idx = j - PREP_NC - PREP_NW1;
        int blk = idx >> 5, l = idx & 31;
        int n8 = blk >> 5, kb = blk & 31;            // K/16 = 32
        int n = n8 * 8 + (l >> 2), t4 = l & 3;
        int k0 = kb * 16 + t4;
        uint4 t;
        t.x = f2tf32(W2[(size_t)(k0     ) * F_OUT + n]);
        t.y = f2tf32(W2[(size_t)(k0 +  4) * F_OUT + n]);
        t.z = f2tf32(W2[(size_t)(k0 +  8) * F_OUT + n]);
        t.w = f2tf32(W2[(size_t)(k0 + 12) * F_OUT + n]);
        reinterpret_cast<uint4*>(g_W2t)[idx] = t;
    }
}

// ---------------------------------------------------------------------------
// cp.async 3-stage tf32 mma GEMM on FRAG-major operands, BK=32,
// single barrier per tile, vectorized LDS.128 fragment loads.
// L1=true : BM=128,BN=128; 8 warps 2m x 4n (warp 64x32), K=256, A=g_A,
//           out = g_h (FRAG-A, K=512) with bias+ReLU.
// L1=false: BM=128,BN= 64; 8 warps 4m x 2n (warp 32x32), K=512, A=g_h,
//           out = Cout fp32 row-major with bias.
// ---------------------------------------------------------------------------
template <bool L1>
__global__ void __launch_bounds__(256, 2)
gemm_frag_kernel(const uint32_t* __restrict__ Aglob,
                 const uint32_t* __restrict__ Bglob,
                 const float* __restrict__ bias,
                 float* __restrict__ Cout)
{
    constexpr int K   = L1 ? 256 : 512;
    constexpr int BN  = L1 ? 128 : 64;
    constexpr int MT  = L1 ? 4 : 2;
    constexpr int NTILES = K / 32;
    constexpr int A_STW  = 128 * 32;                // 4096 words
    constexpr int B_STW  = BN * 32;
    constexpr int STW    = A_STW + B_STW;
    constexpr int BCH    = BN / 32;                 // B chunks/thread (4 or 2)
    constexpr int KB8    = K / 8;
    constexpr int KB16   = K / 16;

    extern __shared__ uint32_t smem[];
    const uint32_t sbase = smem_u32(smem);

    const int tid  = threadIdx.x;
    const int lane = tid & 31;
    const int warp = tid >> 5;
    const int m0 = blockIdx.y * 128;
    const int n0 = blockIdx.x * BN;
    const int warp_m = L1 ? ((warp >> 2) * 64) : ((warp >> 1) * 32);
    const int warp_n = L1 ? ((warp & 3) * 32) : ((warp & 1) * 32);
    const int g  = lane >> 2;
    const int t4 = lane & 3;

    float acc[MT][4][4];
    #pragma unroll
    for (int mt = 0; mt < MT; ++mt)
        #pragma unroll
        for (int nt = 0; nt < 4; ++nt)
            #pragma unroll
            for (int i = 0; i < 4; ++i) acc[mt][nt][i] = 0.f;

    auto issue = [&](int tile, int slot) {
        const int kb8  = tile * 4;
        const int kb16 = tile * 2;
        uint32_t ab = sbase + (uint32_t)(slot * STW) * 4;
        uint32_t bb = ab + A_STW * 4;
        #pragma unroll
        for (int i = 0; i < 4; ++i) {                 // A: 1024 chunks
            int e = tid + i * 256;
            int a_l = e >> 7, b_l = (e >> 5) & 3, l = e & 31;
            const uint32_t* src = Aglob +
                ((size_t)((m0 >> 4) + a_l) * KB8 + kb8 + b_l) * 128 + l * 4;
            asm volatile("cp.async.cg.shared.global [%0], [%1], 16;"
                :: "r"(ab + (uint32_t)(((a_l * 4 + b_l) * 32 + l) * 16)),
                   "l"(src) : "memory");
        }
        #pragma unroll
        for (int i = 0; i < BCH; ++i) {               // B: BN*8 chunks
            int e = tid + i * 256;
            int n_l = e >> 6, p = (e >> 5) & 1, l = e & 31;
            const uint32_t* src = Bglob +
                ((size_t)((n0 >> 3) + n_l) * KB16 + kb16 + p) * 128 + l * 4;
            asm volatile("cp.async.cg.shared.global [%0], [%1], 16;"
                :: "r"(bb + (uint32_t)(((n_l * 2 + p) * 32 + l) * 16)),
                   "l"(src) : "memory");
        }
    };

    issue(0, 0); asm volatile("cp.async.commit_group;" ::: "memory");
    issue(1, 1); asm volatile("cp.async.commit_group;" ::: "memory");

    for (int it = 0; it < NTILES; ++it) {
        asm volatile("cp.async.wait_group 1;" ::: "memory");
        __syncthreads();
        // single barrier: all warps finished compute(it-1); slot (it+2)%3
        // == (it-1)%3 is safe to overwrite.
        if (it + 2 < NTILES) issue(it + 2, (it + 2) % 3);
        asm volatile("cp.async.commit_group;" ::: "memory");

        const uint4* As4 = reinterpret_cast<const uint4*>(smem + (it % 3) * STW);
        const uint4* Bs4 = As4 + A_STW / 4;

        #pragma unroll
        for (int p = 0; p < 2; ++p) {                  // k16 pair
            uint4 bfr[4];
            #pragma unroll
            for (int nt = 0; nt < 4; ++nt) {
                int n_l = (warp_n >> 3) + nt;
                bfr[nt] = Bs4[(n_l * 2 + p) * 32 + lane];
            }
            #pragma unroll
            for (int half = 0; half < 2; ++half) {
                const int ks = p * 2 + half;
                uint4 afr[MT];
                #pragma unroll
                for (int mt = 0; mt < MT; ++mt) {
                    int a_l = (warp_m >> 4) + mt;
                    afr[mt] = As4[(a_l * 4 + ks) * 32 + lane];
                }
                #pragma unroll
                for (int mt = 0; mt < MT; ++mt)
                    #pragma unroll
                    for (int nt = 0; nt < 4; ++nt) {
                        uint32_t b0 = half ? bfr[nt].z : bfr[nt].x;
                        uint32_t b1 = half ? bfr[nt].w : bfr[nt].y;
                        asm volatile(
                            "mma.sync.aligned.m16n8k8.row.col.f32.tf32.tf32.f32 "
                            "{%0,%1,%2,%3}, {%4,%5,%6,%7}, {%8,%9}, {%0,%1,%2,%3};"
                            : "+f"(acc[mt][nt][0]), "+f"(acc[mt][nt][1]),
                              "+f"(acc[mt][nt][2]), "+f"(acc[mt][nt][3])
                            : "r"(afr[mt].x), "r"(afr[mt].y),
                              "r"(afr[mt].z), "r"(afr[mt].w),
                              "r"(b0), "r"(b1));
                    }
            }
        }
    }

    // ---- epilogue ----
    #pragma unroll
    for (int mt = 0; mt < MT; ++mt) {
        #pragma unroll
        for (int nt = 0; nt < 4; ++nt) {
            int gc = n0 + warp_n + nt * 8 + t4 * 2;
            float2 bv = *reinterpret_cast<const float2*>(bias + gc);
            #pragma unroll
            for (int hh = 0; hh < 2; ++hh) {
                int gr = m0 + warp_m + mt * 16 + g + hh * 8;
                if (gr >= N_NODES) continue;
                float ox = acc[mt][nt][hh * 2 + 0] + bv.x;
                float oy = acc[mt][nt][hh * 2 + 1] + bv.y;
                if (L1) {
                    // store into g_h FRAG-A (K=512): two scalar words
                    uint32_t tx = f2tf32(fmaxf(ox, 0.f));
                    uint32_t ty = f2tf32(fmaxf(oy, 0.f));
                    size_t base = ((size_t)(gr >> 4) * 64 + (gc >> 3)) * 128;
                    int wr = (gr >> 3) & 1;
                    size_t a0 = base + (4 * (gr & 7) + (gc & 3)) * 4
                                     + ((gc >> 2) & 1) * 2 + wr;
                    int gc1 = gc + 1;
                    size_t a1 = base + (4 * (gr & 7) + (gc1 & 3)) * 4
                                     + ((gc1 >> 2) & 1) * 2 + wr;
                    g_h[a0] = tx;
                    g_h[a1] = ty;
                } else {
                    float2 o = make_float2(ox, oy);
                    *reinterpret_cast<float2*>(Cout + (size_t)gr * F_OUT + gc) = o;
                }
            }
        }
    }
}

// ---------------------------------------------------------------------------
// order: memset(agg) -> scatter -> prep -> gemm1 -> gemm2
// Inputs: nodes, edge_attr, senders, receivers, W1, b1, W2, b2
// ---------------------------------------------------------------------------
extern "C" void kernel_launch(void* const* d_in, const int* in_sizes, int n_in,
                              void* d_out, int out_size)
{
    const float*  nodes     = (const float*)d_in[0];
    const float4* edge_attr = (const float4*)d_in[1];
    const int*    receivers = (const int*)d_in[3];
    const float*  W1        = (const float*)d_in[4];
    const float*  b1        = (const float*)d_in[5];
    const float*  W2        = (const float*)d_in[6];
    const float*  b2        = (const float*)d_in[7];
    float* out = (float*)d_out;

    uint32_t *w1t = nullptr, *w2t = nullptr, *gA = nullptr, *gh = nullptr;
    float* gagg = nullptr;
    cudaGetSymbolAddress((void**)&w1t,  g_W1t);
    cudaGetSymbolAddress((void**)&w2t,  g_W2t);
    cudaGetSymbolAddress((void**)&gA,   g_A);
    cudaGetSymbolAddress((void**)&gh,   g_h);
    cudaGetSymbolAddress((void**)&gagg, g_agg);

    constexpr int SMEM1 = 3 * (128 + 128) * 32 * 4;   // 98,304 B
    constexpr int SMEM2 = 3 * (128 +  64) * 32 * 4;   // 73,728 B

    static bool attr_set = false;
    if (!attr_set) {
        cudaFuncSetAttribute(gemm_frag_kernel<true>,
                             cudaFuncAttributeMaxDynamicSharedMemorySize, SMEM1);
        cudaFuncSetAttribute(gemm_frag_kernel<false>,
                             cudaFuncAttributeMaxDynamicSharedMemorySize, SMEM2);
        attr_set = true;
    }

    // 1) zero agg
    cudaMemsetAsync(gagg, 0, (size_t)N_NODES * F_E * sizeof(float));

    // 2) scatter
    {
        long long total = (long long)N_EDGES * 32;
        int blocks = (int)((total + 255) / 256);
        scatter_edges_kernel<<<blocks, 256>>>(edge_attr, receivers);
    }
    // 3) prep (FRAG-major operand builds)
    prep_kernel<<<(PREP_TOTAL + 255) / 256, 256>>>(nodes, W1, W2);
    // 4) gemm1: grid (4, 391)
    {
        dim3 grid(HIDDEN / 128, (N_NODES + 127) / 128);
        gemm_frag_kernel<true><<<grid, 256, SMEM1>>>(gA, w1t, b1, nullptr);
    }
    // 5) gemm2: grid (2, 391)
    {
        dim3 grid(F_OUT / 64, (N_NODES + 127) / 128);
        gemm_frag_kernel<false><<<grid, 256, SMEM2>>>(gh, w2t, b2, out);
    }
}

// round 14
// speedup vs baseline: 1.5228x; 1.0267x over previous
#include <cuda_runtime.h>
#include <cstdint>

#define N_NODES 50000
#define N_EDGES 800000
#define F_X 128
#define F_E 128
#define HIDDEN 512
#define F_OUT 128
#define M_BLKS 3128                    // ceil(50000/16) padded to 128-row CTAs

// ---------------- scratch (static device globals; no runtime alloc) --------
// FRAG-A layout: word(r,c) = ((r>>4)*(K/8) + (c>>3))*128
//                            + (4*(r&7)+(c&3))*4 + ((c>>2)&1)*2 + ((r>>3)&1)
// FRAG-B layout: word(n,k) = ((n>>3)*(K/16) + (k>>4))*128
//                            + (4*(n&7)+(k&3))*4 + ((k>>3)&1)*2 + ((k>>2)&1)
__device__ float    g_agg[(size_t)N_NODES * F_E];                 // 25.6 MB
__device__ uint32_t g_A[(size_t)M_BLKS * 32 * 128];               // 51.3 MB, K=256
__device__ uint32_t g_h[(size_t)M_BLKS * 64 * 128];               // 102.5 MB, K=512
__device__ uint32_t g_W1t[(size_t)HIDDEN * (F_E + F_X)];          // FRAG-B K=256
__device__ uint32_t g_W2t[(size_t)F_OUT * HIDDEN];                // FRAG-B K=512

__device__ __forceinline__ uint32_t f2tf32(float f) {
    uint32_t r; asm("cvt.rna.tf32.f32 %0, %1;" : "=r"(r) : "f"(f)); return r;
}
__device__ __forceinline__ uint32_t smem_u32(const void* p) {
    uint32_t a;
    asm("{ .reg .u64 t; cvta.to.shared.u64 t, %1; cvt.u32.u64 %0, t; }"
        : "=r"(a) : "l"(p));
    return a;
}

// ---------------------------------------------------------------------------
// scatter-add, one warp per edge, red.global.add.v4.f32
// ---------------------------------------------------------------------------
__global__ void __launch_bounds__(256) scatter_edges_kernel(
    const float4* __restrict__ edge_attr, const int* __restrict__ receivers)
{
    int gt = blockIdx.x * blockDim.x + threadIdx.x;
    int edge = gt >> 5;
    int lane = gt & 31;
    if (edge >= N_EDGES) return;

    int r = __ldg(receivers + edge);
    float4 v = edge_attr[(size_t)edge * 32 + lane];
    float* dst = g_agg + (size_t)r * F_E + lane * 4;
    asm volatile("red.global.add.v4.f32 [%0], {%1,%2,%3,%4};"
                 :: "l"(dst), "f"(v.x), "f"(v.y), "f"(v.z), "f"(v.w)
                 : "memory");
}

// ---------------------------------------------------------------------------
// prep: build FRAG-A g_A from [agg|nodes], FRAG-B g_W1t / g_W2t.
// item = one 16B chunk (= one lane's 4 fragment words).
// ---------------------------------------------------------------------------
#define PREP_NC   (3125 * 32 * 32)               // 3,200,000 A chunks
#define PREP_NW1  ((HIDDEN / 8) * (256 / 16) * 32)   // 32768
#define PREP_NW2  ((F_OUT / 8) * (512 / 16) * 32)    // 16384
#define PREP_TOTAL (PREP_NC + PREP_NW1 + PREP_NW2)

__global__ void __launch_bounds__(256) prep_kernel(
    const float* __restrict__ nodes,
    const float* __restrict__ W1, const float* __restrict__ W2)
{
    int j = blockIdx.x * blockDim.x + threadIdx.x;
    if (j < PREP_NC) {
        int a = j >> 10, b = (j >> 5) & 31, l = j & 31;
        int gg = l >> 2, t4 = l & 3;
        int r = a * 16 + gg;
        int c = b * 8 + t4;
        const float* s0 = (c < F_E) ? (g_agg + c) : (nodes + c - F_E);
        const float* s1 = (c + 4 < F_E) ? (g_agg + c + 4) : (nodes + c + 4 - F_E);
        uint4 t;
        t.x = f2tf32(s0[(size_t)r * 128]);
        t.y = f2tf32(s0[(size_t)(r + 8) * 128]);
        t.z = f2tf32(s1[(size_t)r * 128]);
        t.w = f2tf32(s1[(size_t)(r + 8) * 128]);
        reinterpret_cast<uint4*>(g_A)[j] = t;
    } else if (j < PREP_NC + PREP_NW1) {
        int idx = j - PREP_NC;
        int blk = idx >> 5, l = idx & 31;
        int n8 = blk >> 4, kb = blk & 15;            // K/16 = 16
        int n = n8 * 8 + (l >> 2), t4 = l & 3;
        int k0 = kb * 16 + t4;
        uint4 t;
        t.x = f2tf32(W1[(size_t)(k0     ) * HIDDEN + n]);
        t.y = f2tf32(W1[(size_t)(k0 +  4) * HIDDEN + n]);
        t.z = f2tf32(W1[(size_t)(k0 +  8) * HIDDEN + n]);
        t.w = f2tf32(W1[(size_t)(k0 + 12) * HIDDEN + n]);
        reinterpret_cast<uint4*>(g_W1t)[idx] = t;
    } else if (j < PREP_TOTAL) {
        int idx = j - PREP_NC - PREP_NW1;
        int blk = idx >> 5, l = idx & 31;
        int n8 = blk >> 5, kb = blk & 31;            // K/16 = 32
        int n = n8 * 8 + (l >> 2), t4 = l & 3;
        int k0 = kb * 16 + t4;
        uint4 t;
        t.x = f2tf32(W2[(size_t)(k0     ) * F_OUT + n]);
        t.y = f2tf32(W2[(size_t)(k0 +  4) * F_OUT + n]);
        t.z = f2tf32(W2[(size_t)(k0 +  8) * F_OUT + n]);
        t.w = f2tf32(W2[(size_t)(k0 + 12) * F_OUT + n]);
        reinterpret_cast<uint4*>(g_W2t)[idx] = t;
    }
}

// ---------------------------------------------------------------------------
// cp.async 3-stage tf32 mma GEMM on FRAG-major operands.
// Unified shape: BM=128, BN=64, BK=32; 8 warps 4m x 2n (warp 32x32), MT=2.
// 3 CTAs/SM (launch_bounds(256,3), 73.7 KB smem, regs capped 84).
// L1=true : K=256, A=g_A, out=g_h (FRAG-A K=512) bias+ReLU. grid (8,391).
// L1=false: K=512, A=g_h, out=Cout fp32 row-major bias.     grid (2,391).
// ---------------------------------------------------------------------------
template <bool L1>
__global__ void __launch_bounds__(256, 3)
gemm_frag_kernel(const uint32_t* __restrict__ Aglob,
                 const uint32_t* __restrict__ Bglob,
                 const float* __restrict__ bias,
                 float* __restrict__ Cout)
{
    constexpr int K   = L1 ? 256 : 512;
    constexpr int BN  = 64;
    constexpr int MT  = 2;
    constexpr int NTILES = K / 32;
    constexpr int A_STW  = 128 * 32;                // 4096 words
    constexpr int B_STW  = BN * 32;                 // 2048 words
    constexpr int STW    = A_STW + B_STW;           // 6144 words / stage
    constexpr int KB8    = K / 8;
    constexpr int KB16   = K / 16;

    extern __shared__ uint32_t smem[];
    const uint32_t sbase = smem_u32(smem);

    const int tid  = threadIdx.x;
    const int lane = tid & 31;
    const int warp = tid >> 5;
    const int m0 = blockIdx.y * 128;
    const int n0 = blockIdx.x * BN;
    const int warp_m = (warp >> 1) * 32;
    const int warp_n = (warp & 1) * 32;
    const int g  = lane >> 2;
    const int t4 = lane & 3;

    float acc[MT][4][4];
    #pragma unroll
    for (int mt = 0; mt < MT; ++mt)
        #pragma unroll
        for (int nt = 0; nt < 4; ++nt)
            #pragma unroll
            for (int i = 0; i < 4; ++i) acc[mt][nt][i] = 0.f;

    auto issue = [&](int tile, int slot) {
        const int kb8  = tile * 4;
        const int kb16 = tile * 2;
        uint32_t ab = sbase + (uint32_t)(slot * STW) * 4;
        uint32_t bb = ab + A_STW * 4;
        #pragma unroll
        for (int i = 0; i < 4; ++i) {                 // A: 1024 chunks
            int e = tid + i * 256;
            int a_l = e >> 7, b_l = (e >> 5) & 3, l = e & 31;
            const uint32_t* src = Aglob +
                ((size_t)((m0 >> 4) + a_l) * KB8 + kb8 + b_l) * 128 + l * 4;
            asm volatile("cp.async.cg.shared.global [%0], [%1], 16;"
                :: "r"(ab + (uint32_t)(((a_l * 4 + b_l) * 32 + l) * 16)),
                   "l"(src) : "memory");
        }
        #pragma unroll
        for (int i = 0; i < 2; ++i) {                 // B: 512 chunks
            int e = tid + i * 256;
            int n_l = e >> 6, p = (e >> 5) & 1, l = e & 31;
            const uint32_t* src = Bglob +
                ((size_t)((n0 >> 3) + n_l) * KB16 + kb16 + p) * 128 + l * 4;
            asm volatile("cp.async.cg.shared.global [%0], [%1], 16;"
                :: "r"(bb + (uint32_t)(((n_l * 2 + p) * 32 + l) * 16)),
                   "l"(src) : "memory");
        }
    };

    issue(0, 0); asm volatile("cp.async.commit_group;" ::: "memory");
    issue(1, 1); asm volatile("cp.async.commit_group;" ::: "memory");

    for (int it = 0; it < NTILES; ++it) {
        asm volatile("cp.async.wait_group 1;" ::: "memory");
        __syncthreads();
        // single barrier: all warps finished compute(it-1); slot (it+2)%3
        // == (it-1)%3 is safe to overwrite.
        if (it + 2 < NTILES) issue(it + 2, (it + 2) % 3);
        asm volatile("cp.async.commit_group;" ::: "memory");

        const uint4* As4 = reinterpret_cast<const uint4*>(smem + (it % 3) * STW);
        const uint4* Bs4 = As4 + A_STW / 4;

        #pragma unroll
        for (int p = 0; p < 2; ++p) {                  // k16 pair
            uint4 bfr[4];
            #pragma unroll
            for (int nt = 0; nt < 4; ++nt) {
                int n_l = (warp_n >> 3) + nt;
                bfr[nt] = Bs4[(n_l * 2 + p) * 32 + lane];
            }
            #pragma unroll
            for (int half = 0; half < 2; ++half) {
                const int ks = p * 2 + half;
                uint4 afr[MT];
                #pragma unroll
                for (int mt = 0; mt < MT; ++mt) {
                    int a_l = (warp_m >> 4) + mt;
                    afr[mt] = As4[(a_l * 4 + ks) * 32 + lane];
                }
                #pragma unroll
                for (int mt = 0; mt < MT; ++mt)
                    #pragma unroll
                    for (int nt = 0; nt < 4; ++nt) {
                        uint32_t b0 = half ? bfr[nt].z : bfr[nt].x;
                        uint32_t b1 = half ? bfr[nt].w : bfr[nt].y;
                        asm volatile(
                            "mma.sync.aligned.m16n8k8.row.col.f32.tf32.tf32.f32 "
                            "{%0,%1,%2,%3}, {%4,%5,%6,%7}, {%8,%9}, {%0,%1,%2,%3};"
                            : "+f"(acc[mt][nt][0]), "+f"(acc[mt][nt][1]),
                              "+f"(acc[mt][nt][2]), "+f"(acc[mt][nt][3])
                            : "r"(afr[mt].x), "r"(afr[mt].y),
                              "r"(afr[mt].z), "r"(afr[mt].w),
                              "r"(b0), "r"(b1));
                    }
            }
        }
    }

    // ---- epilogue ----
    #pragma unroll
    for (int mt = 0; mt < MT; ++mt) {
        #pragma unroll
        for (int nt = 0; nt < 4; ++nt) {
            int gc = n0 + warp_n + nt * 8 + t4 * 2;
            float2 bv = *reinterpret_cast<const float2*>(bias + gc);
            #pragma unroll
            for (int hh = 0; hh < 2; ++hh) {
                int gr = m0 + warp_m + mt * 16 + g + hh * 8;
                if (gr >= N_NODES) continue;
                float ox = acc[mt][nt][hh * 2 + 0] + bv.x;
                float oy = acc[mt][nt][hh * 2 + 1] + bv.y;
                if (L1) {
                    // store into g_h FRAG-A (K=512): two scalar words
                    uint32_t tx = f2tf32(fmaxf(ox, 0.f));
                    uint32_t ty = f2tf32(fmaxf(oy, 0.f));
                    size_t base = ((size_t)(gr >> 4) * 64 + (gc >> 3)) * 128;
                    int wr = (gr >> 3) & 1;
                    size_t a0 = base + (4 * (gr & 7) + (gc & 3)) * 4
                                     + ((gc >> 2) & 1) * 2 + wr;
                    int gc1 = gc + 1;
                    size_t a1 = base + (4 * (gr & 7) + (gc1 & 3)) * 4
                                     + ((gc1 >> 2) & 1) * 2 + wr;
                    g_h[a0] = tx;
                    g_h[a1] = ty;
                } else {
                    float2 o = make_float2(ox, oy);
                    *reinterpret_cast<float2*>(Cout + (size_t)gr * F_OUT + gc) = o;
                }
            }
        }
    }
}

// ---------------------------------------------------------------------------
// order: memset(agg) -> scatter -> prep -> gemm1 -> gemm2
// Inputs: nodes, edge_attr, senders, receivers, W1, b1, W2, b2
// ---------------------------------------------------------------------------
extern "C" void kernel_launch(void* const* d_in, const int* in_sizes, int n_in,
                              void* d_out, int out_size)
{
    const float*  nodes     = (const float*)d_in[0];
    const float4* edge_attr = (const float4*)d_in[1];
    const int*    receivers = (const int*)d_in[3];
    const float*  W1        = (const float*)d_in[4];
    const float*  b1        = (const float*)d_in[5];
    const float*  W2        = (const float*)d_in[6];
    const float*  b2        = (const float*)d_in[7];
    float* out = (float*)d_out;

    uint32_t *w1t = nullptr, *w2t = nullptr, *gA = nullptr, *gh = nullptr;
    float* gagg = nullptr;
    cudaGetSymbolAddress((void**)&w1t,  g_W1t);
    cudaGetSymbolAddress((void**)&w2t,  g_W2t);
    cudaGetSymbolAddress((void**)&gA,   g_A);
    cudaGetSymbolAddress((void**)&gh,   g_h);
    cudaGetSymbolAddress((void**)&gagg, g_agg);

    constexpr int SMEM = 3 * (128 + 64) * 32 * 4;   // 73,728 B (both gemms)

    static bool attr_set = false;
    if (!attr_set) {
        cudaFuncSetAttribute(gemm_frag_kernel<true>,
                             cudaFuncAttributeMaxDynamicSharedMemorySize, SMEM);
        cudaFuncSetAttribute(gemm_frag_kernel<false>,
                             cudaFuncAttributeMaxDynamicSharedMemorySize, SMEM);
        attr_set = true;
    }

    // 1) zero agg
    cudaMemsetAsync(gagg, 0, (size_t)N_NODES * F_E * sizeof(float));

    // 2) scatter
    {
        long long total = (long long)N_EDGES * 32;
        int blocks = (int)((total + 255) / 256);
        scatter_edges_kernel<<<blocks, 256>>>(edge_attr, receivers);
    }
    // 3) prep (FRAG-major operand builds)
    prep_kernel<<<(PREP_TOTAL + 255) / 256, 256>>>(nodes, W1, W2);
    // 4) gemm1: grid (8, 391)
    {
        dim3 grid(HIDDEN / 64, (N_NODES + 127) / 128);
        gemm_frag_kernel<true><<<grid, 256, SMEM>>>(gA, w1t, b1, nullptr);
    }
    // 5) gemm2: grid (2, 391)
    {
        dim3 grid(F_OUT / 64, (N_NODES + 127) / 128);
        gemm_frag_kernel<false><<<grid, 256, SMEM>>>(gh, w2t, b2, out);
    }
}